// round 14
// baseline (speedup 1.0000x reference)
#include <cuda_runtime.h>
#include <math.h>
#include <stdint.h>

#define D1 256
#define C2 40
#define MAXN 50176
#define MAXE 800000
#define MAXET (MAXE + MAXN)

// ---------------- static scratch (no runtime allocation) ----------------
__device__ float    g_xl1[(size_t)MAXN * D1];
__device__ float    g_xr1[(size_t)MAXN * D1];
__device__ float    g_h1 [(size_t)MAXN * D1];
__device__ float    g_xl2[(size_t)MAXN * C2];
__device__ float    g_xr2[(size_t)MAXN * C2];
__device__ uint32_t g_xt [(size_t)MAXN * 128];   // x pre-converted to tf32
__device__ int      g_counts[MAXN + 1];          // zero-init; re-zeroed by attn1 each run
__device__ int      g_offs  [MAXN + 1];
__device__ int      g_cursor[MAXN + 1];
__device__ int      g_src[MAXET];
__device__ float    g_bn[512];                   // zero-init; re-zeroed by attn2 each run
__device__ uint32_t g_W1t[128 * 512];   // [Wl1 | Wr1] tf32
__device__ uint32_t g_W2t[256 * 80];    // [Wl2 | Wr2] tf32

__device__ __forceinline__ uint32_t f2tf32(float f) {
    uint32_t r;
    asm("cvt.rna.tf32.f32 %0, %1;" : "=r"(r) : "f"(f));
    return r;
}

__device__ __forceinline__ void mma_tf32(float c[4], const uint32_t a[4],
                                         uint32_t b0, uint32_t b1) {
    asm volatile(
        "mma.sync.aligned.m16n8k8.row.col.f32.tf32.tf32.f32 "
        "{%0,%1,%2,%3}, {%4,%5,%6,%7}, {%8,%9}, {%0,%1,%2,%3};"
        : "+f"(c[0]), "+f"(c[1]), "+f"(c[2]), "+f"(c[3])
        : "r"(a[0]), "r"(a[1]), "r"(a[2]), "r"(a[3]), "r"(b0), "r"(b1));
}

__device__ __forceinline__ void cp_async16(uint32_t smem_addr, const void* gptr) {
    asm volatile("cp.async.cg.shared.global [%0], [%1], 16;"
                 :: "r"(smem_addr), "l"(gptr));
}

// ---------------- fused pre-pass: count | w1cat | w2cat | x-convert ----------------
__global__ void k_pre(const int* __restrict__ ei, int E, int N, int G,
                      int CB, int W1B, int W2B,
                      const float* __restrict__ x,
                      const float* __restrict__ Wl1, const float* __restrict__ Wr1,
                      const float* __restrict__ Wl2, const float* __restrict__ Wr2)
{
    int b = blockIdx.x, tid = threadIdx.x;
    if (b < CB) {
        int t = b * 256 + tid;
        if (t >= G) return;
        int ET = E + N;
#pragma unroll
        for (int q = 0; q < 4; q++) {
            int i = t + q * G;
            if (i < ET) {
                int dst = (i < E) ? ei[E + i] : (i - E);
                atomicAdd(&g_counts[dst], 1);
            }
        }
    } else if (b < CB + W1B) {
        int i = (b - CB) * 256 + tid;
        int k = i >> 9, c = i & 511;
        float v = (c < 256) ? Wl1[k * 256 + c] : Wr1[k * 256 + (c - 256)];
        g_W1t[i] = f2tf32(v);
    } else if (b < CB + W1B + W2B) {
        int i = (b - CB - W1B) * 256 + tid;
        if (i < 256 * 80) {
            int k = i / 80, c = i % 80;
            float v = (c < 40) ? Wl2[k * 40 + c] : Wr2[k * 40 + (c - 40)];
            g_W2t[i] = f2tf32(v);
        }
    } else {
        int i = (b - CB - W1B - W2B) * 256 + tid;
        if (i < N * 32) {
            float4 v = ((const float4*)x)[i];
            ((uint4*)g_xt)[i] = make_uint4(f2tf32(v.x), f2tf32(v.y),
                                           f2tf32(v.z), f2tf32(v.w));
        }
    }
}

// ---------------- scan: 4 elements per thread ----------------
__global__ void k_scan(int n) {
    __shared__ int wsum[32];
    __shared__ int s_carry;
    int t = threadIdx.x, lane = t & 31, w = t >> 5;
    if (t == 0) s_carry = 0;
    __syncthreads();
    for (int base = 0; base < n; base += 4096) {
        int i0 = base + t * 4;
        int v0 = (i0 + 0 < n) ? g_counts[i0 + 0] : 0;
        int v1 = (i0 + 1 < n) ? g_counts[i0 + 1] : 0;
        int v2 = (i0 + 2 < n) ? g_counts[i0 + 2] : 0;
        int v3 = (i0 + 3 < n) ? g_counts[i0 + 3] : 0;
        int sum4 = v0 + v1 + v2 + v3;
        int s = sum4;
#pragma unroll
        for (int o = 1; o < 32; o <<= 1) {
            int y = __shfl_up_sync(0xffffffffu, s, o);
            if (lane >= o) s += y;
        }
        if (lane == 31) wsum[w] = s;
        __syncthreads();
        if (w == 0) {
            int ws = wsum[lane];
#pragma unroll
            for (int o = 1; o < 32; o <<= 1) {
                int y = __shfl_up_sync(0xffffffffu, ws, o);
                if (lane >= o) ws += y;
            }
            wsum[lane] = ws;
        }
        __syncthreads();
        int excl = s_carry + (w > 0 ? wsum[w - 1] : 0) + (s - sum4);
        if (i0 + 0 < n) { g_offs[i0 + 0] = excl;           g_cursor[i0 + 0] = excl; }
        if (i0 + 1 < n) { g_offs[i0 + 1] = excl + v0;      g_cursor[i0 + 1] = excl + v0; }
        if (i0 + 2 < n) { g_offs[i0 + 2] = excl + v0 + v1; g_cursor[i0 + 2] = excl + v0 + v1; }
        if (i0 + 3 < n) { g_offs[i0 + 3] = excl + v0 + v1 + v2;
                          g_cursor[i0 + 3] = excl + v0 + v1 + v2; }
        int total = wsum[31];
        __syncthreads();
        if (t == 0) s_carry += total;
        __syncthreads();
    }
    if (t == 0) g_offs[n] = s_carry;
}

// ---------------- fused: CSR fill | layer-1 tf32 GEMM (cp.async double buffer) ----------------
#define KC 16
#define SAW 20
#define SBW 136
__global__ __launch_bounds__(512, 2) void k_fill_gemm1(
    const int* __restrict__ ei, int E, int N, int G, int FB,
    float* __restrict__ outL, float* __restrict__ outR, int M)
{
    __shared__ uint32_t As[2][128 * SAW];
    __shared__ uint32_t Bs[2][KC * SBW];
    int tid = threadIdx.x;

    if (blockIdx.x < FB) {              // ---- CSR fill ----
        int t = blockIdx.x * 512 + tid;
        if (t >= G) return;
        int ET = E + N;
#pragma unroll
        for (int q = 0; q < 4; q++) {
            int i = t + q * G;
            if (i < ET) {
                int src, dst;
                if (i < E) { src = ei[i]; dst = ei[E + i]; } else { src = dst = i - E; }
                int p = atomicAdd(&g_cursor[dst], 1);
                g_src[p] = src;
            }
        }
        return;
    }

    // ---- GEMM: C[M,512] = xt[M,128] @ W1t[128,512] ----
    int flat = blockIdx.x - FB;
    int n0 = (flat & 3) << 7;
    int m0 = (flat >> 2) << 7;
    int lane = tid & 31, wid = tid >> 5;
    int warp_m = wid >> 2, warp_n = wid & 3;
    float acc[2][4][4] = {};

    int ar = tid >> 2, aq = (tid & 3) * 4;
    int bk = tid >> 5, bc = (tid & 31) * 4;
    const uint32_t* gA = &g_xt[(size_t)(m0 + ar) * 128 + aq];
    const uint32_t* gB = &g_W1t[(size_t)bk * 512 + n0 + bc];

    uint32_t sA0 = (uint32_t)__cvta_generic_to_shared(&As[0][ar * SAW + aq]);
    uint32_t sA1 = (uint32_t)__cvta_generic_to_shared(&As[1][ar * SAW + aq]);
    uint32_t sB0 = (uint32_t)__cvta_generic_to_shared(&Bs[0][bk * SBW + bc]);
    uint32_t sB1 = (uint32_t)__cvta_generic_to_shared(&Bs[1][bk * SBW + bc]);

    cp_async16(sA0, gA);
    cp_async16(sB0, gB);
    asm volatile("cp.async.commit_group;");

#pragma unroll
    for (int it = 0; it < 8; it++) {
        int buf = it & 1;
        if (it < 7) {
            int k0 = (it + 1) * KC;
            cp_async16(buf ? sA0 : sA1, gA + k0);
            cp_async16(buf ? sB0 : sB1, gB + (size_t)k0 * 512);
            asm volatile("cp.async.commit_group;");
            asm volatile("cp.async.wait_group 1;");
        } else {
            asm volatile("cp.async.wait_group 0;");
        }
        __syncthreads();

        const uint32_t* Ab = As[buf];
        const uint32_t* Bb = Bs[buf];
#pragma unroll
        for (int ks = 0; ks < 2; ks++) {
            int kc = ks * 8 + (lane & 3);
            uint32_t a[2][4];
            int r0 = warp_m * 32 + (lane >> 2);
#pragma unroll
            for (int mi = 0; mi < 2; mi++) {
                int r = r0 + mi * 16;
                a[mi][0] = Ab[r * SAW + kc];
                a[mi][1] = Ab[(r + 8) * SAW + kc];
                a[mi][2] = Ab[r * SAW + kc + 4];
                a[mi][3] = Ab[(r + 8) * SAW + kc + 4];
            }
#pragma unroll
            for (int nj = 0; nj < 4; nj++) {
                int n = warp_n * 32 + nj * 8 + (lane >> 2);
                uint32_t b0 = Bb[kc * SBW + n];
                uint32_t b1 = Bb[(kc + 4) * SBW + n];
                mma_tf32(acc[0][nj], a[0], b0, b1);
                mma_tf32(acc[1][nj], a[1], b0, b1);
            }
        }
        __syncthreads();
    }

    float* O = (n0 < 256) ? outL : outR;
    int nb = n0 & 255;
#pragma unroll
    for (int mi = 0; mi < 2; mi++) {
        int r = m0 + warp_m * 32 + mi * 16 + (lane >> 2);
#pragma unroll
        for (int nj = 0; nj < 4; nj++) {
            int nc = nb + warp_n * 32 + nj * 8 + (lane & 3) * 2;
            if (r < M)
                *(float2*)&O[(size_t)r * 256 + nc] =
                    make_float2(acc[mi][nj][0], acc[mi][nj][1]);
            if (r + 8 < M)
                *(float2*)&O[(size_t)(r + 8) * 256 + nc] =
                    make_float2(acc[mi][nj][2], acc[mi][nj][3]);
        }
    }
}

// ---------------- layer-1 fused attention (4-edge ILP unroll) ----------------
__global__ __launch_bounds__(256) void k_attn1(const float* __restrict__ att,
                                               const float* __restrict__ b1, int N)
{
    int gt = blockIdx.x * blockDim.x + threadIdx.x;
    int w = gt >> 5, lane = gt & 31;
    if (w >= N) return;
    int beg = g_offs[w], end = g_offs[w + 1];
    if (lane == 0) g_counts[w] = 0;      // reset for next replay (CSR already built)

    const float4* pxr = (const float4*)g_xr1 + (size_t)w * 64 + lane * 2;
    float4 r0 = pxr[0], r1 = pxr[1];
    const float4* pa = (const float4*)att + lane * 2;
    float4 at0 = pa[0], at1 = pa[1];

    float mx = -1e30f, dn = 0.f;
    float c0 = 0, c1 = 0, c2 = 0, c3 = 0, c4 = 0, c5 = 0, c6 = 0, c7 = 0;

    int p = beg;
    for (; p + 4 <= end; p += 4) {
        float4 xa0[2], xa1[2], xa2[2], xa3[2];
        {
            int s0i = g_src[p + 0], s1i = g_src[p + 1];
            int s2i = g_src[p + 2], s3i = g_src[p + 3];
            const float4* q0 = (const float4*)g_xl1 + (size_t)s0i * 64 + lane * 2;
            const float4* q1 = (const float4*)g_xl1 + (size_t)s1i * 64 + lane * 2;
            const float4* q2 = (const float4*)g_xl1 + (size_t)s2i * 64 + lane * 2;
            const float4* q3 = (const float4*)g_xl1 + (size_t)s3i * 64 + lane * 2;
            xa0[0] = q0[0]; xa0[1] = q0[1];
            xa1[0] = q1[0]; xa1[1] = q1[1];
            xa2[0] = q2[0]; xa2[1] = q2[1];
            xa3[0] = q3[0]; xa3[1] = q3[1];
        }
        float v, s0 = 0.f, s1 = 0.f, s2 = 0.f, s3 = 0.f;
#define LOGIT8(S, XA) \
        v = XA[0].x + r0.x; S += fmaxf(v, 0.2f * v) * at0.x; \
        v = XA[0].y + r0.y; S += fmaxf(v, 0.2f * v) * at0.y; \
        v = XA[0].z + r0.z; S += fmaxf(v, 0.2f * v) * at0.z; \
        v = XA[0].w + r0.w; S += fmaxf(v, 0.2f * v) * at0.w; \
        v = XA[1].x + r1.x; S += fmaxf(v, 0.2f * v) * at1.x; \
        v = XA[1].y + r1.y; S += fmaxf(v, 0.2f * v) * at1.y; \
        v = XA[1].z + r1.z; S += fmaxf(v, 0.2f * v) * at1.z; \
        v = XA[1].w + r1.w; S += fmaxf(v, 0.2f * v) * at1.w;
        LOGIT8(s0, xa0) LOGIT8(s1, xa1) LOGIT8(s2, xa2) LOGIT8(s3, xa3)
#undef LOGIT8
        s0 += __shfl_xor_sync(0xffffffffu, s0, 4);
        s1 += __shfl_xor_sync(0xffffffffu, s1, 4);
        s2 += __shfl_xor_sync(0xffffffffu, s2, 4);
        s3 += __shfl_xor_sync(0xffffffffu, s3, 4);
        s0 += __shfl_xor_sync(0xffffffffu, s0, 2);
        s1 += __shfl_xor_sync(0xffffffffu, s1, 2);
        s2 += __shfl_xor_sync(0xffffffffu, s2, 2);
        s3 += __shfl_xor_sync(0xffffffffu, s3, 2);
        s0 += __shfl_xor_sync(0xffffffffu, s0, 1);
        s1 += __shfl_xor_sync(0xffffffffu, s1, 1);
        s2 += __shfl_xor_sync(0xffffffffu, s2, 1);
        s3 += __shfl_xor_sync(0xffffffffu, s3, 1);
        float mnew = fmaxf(mx, fmaxf(fmaxf(s0, s1), fmaxf(s2, s3)));
        float sc = __expf(mx - mnew);
        float e0 = __expf(s0 - mnew);
        float e1 = __expf(s1 - mnew);
        float e2 = __expf(s2 - mnew);
        float e3 = __expf(s3 - mnew);
        dn = dn * sc + (e0 + e1) + (e2 + e3);
        c0 = c0 * sc + e0 * xa0[0].x + e1 * xa1[0].x + e2 * xa2[0].x + e3 * xa3[0].x;
        c1 = c1 * sc + e0 * xa0[0].y + e1 * xa1[0].y + e2 * xa2[0].y + e3 * xa3[0].y;
        c2 = c2 * sc + e0 * xa0[0].z + e1 * xa1[0].z + e2 * xa2[0].z + e3 * xa3[0].z;
        c3 = c3 * sc + e0 * xa0[0].w + e1 * xa1[0].w + e2 * xa2[0].w + e3 * xa3[0].w;
        c4 = c4 * sc + e0 * xa0[1].x + e1 * xa1[1].x + e2 * xa2[1].x + e3 * xa3[1].x;
        c5 = c5 * sc + e0 * xa0[1].y + e1 * xa1[1].y + e2 * xa2[1].y + e3 * xa3[1].y;
        c6 = c6 * sc + e0 * xa0[1].z + e1 * xa1[1].z + e2 * xa2[1].z + e3 * xa3[1].z;
        c7 = c7 * sc + e0 * xa0[1].w + e1 * xa1[1].w + e2 * xa2[1].w + e3 * xa3[1].w;
        mx = mnew;
    }
    for (; p < end; p++) {
        int src = g_src[p];
        const float4* pl = (const float4*)g_xl1 + (size_t)src * 64 + lane * 2;
        float4 a0 = pl[0], a1 = pl[1];
        float v, s = 0.f;
        v = a0.x + r0.x; s += fmaxf(v, 0.2f * v) * at0.x;
        v = a0.y + r0.y; s += fmaxf(v, 0.2f * v) * at0.y;
        v = a0.z + r0.z; s += fmaxf(v, 0.2f * v) * at0.z;
        v = a0.w + r0.w; s += fmaxf(v, 0.2f * v) * at0.w;
        v = a1.x + r1.x; s += fmaxf(v, 0.2f * v) * at1.x;
        v = a1.y + r1.y; s += fmaxf(v, 0.2f * v) * at1.y;
        v = a1.z + r1.z; s += fmaxf(v, 0.2f * v) * at1.z;
        v = a1.w + r1.w; s += fmaxf(v, 0.2f * v) * at1.w;
        s += __shfl_xor_sync(0xffffffffu, s, 4);
        s += __shfl_xor_sync(0xffffffffu, s, 2);
        s += __shfl_xor_sync(0xffffffffu, s, 1);
        float mnew = fmaxf(mx, s);
        float sc = __expf(mx - mnew);
        float a = __expf(s - mnew);
        dn = dn * sc + a;
        c0 = c0 * sc + a * a0.x; c1 = c1 * sc + a * a0.y;
        c2 = c2 * sc + a * a0.z; c3 = c3 * sc + a * a0.w;
        c4 = c4 * sc + a * a1.x; c5 = c5 * sc + a * a1.y;
        c6 = c6 * sc + a * a1.z; c7 = c7 * sc + a * a1.w;
        mx = mnew;
    }
    float inv = 1.f / (dn + 1e-16f);
    const float4* pb = (const float4*)b1 + lane * 2;
    float4 bb0 = pb[0], bb1 = pb[1];
    ((float4*)g_h1)[(size_t)w * 64 + lane * 2 + 0] =
        make_float4(c0 * inv + bb0.x, c1 * inv + bb0.y, c2 * inv + bb0.z, c3 * inv + bb0.w);
    ((float4*)g_h1)[(size_t)w * 64 + lane * 2 + 1] =
        make_float4(c4 * inv + bb1.x, c5 * inv + bb1.y, c6 * inv + bb1.z, c7 * inv + bb1.w);
}

// ---------------- batch-norm stats (float4, 64 quads x 4 row-groups) ----------------
__global__ __launch_bounds__(256) void k_bnstats(int N)
{
    __shared__ float sh_s[4 * 256];
    __shared__ float sh_q[4 * 256];
    int tid = threadIdx.x;
    int quad = tid & 63, rg = tid >> 6;       // channel quad, row-group
    int c4 = quad * 4;
    int rend = min(blockIdx.x * 128 + 128, N);
    float4 s = make_float4(0.f, 0.f, 0.f, 0.f);
    float4 q = make_float4(0.f, 0.f, 0.f, 0.f);
    for (int r = blockIdx.x * 128 + rg; r < rend; r += 4) {
        float4 v = *(const float4*)&g_h1[(size_t)r * 256 + c4];
        s.x += v.x; s.y += v.y; s.z += v.z; s.w += v.w;
        q.x += v.x * v.x; q.y += v.y * v.y; q.z += v.z * v.z; q.w += v.w * v.w;
    }
    *(float4*)&sh_s[rg * 256 + c4] = s;
    *(float4*)&sh_q[rg * 256 + c4] = q;
    __syncthreads();
    // threads 0..255: one channel each
    float ts = sh_s[tid] + sh_s[256 + tid] + sh_s[512 + tid] + sh_s[768 + tid];
    float tq = sh_q[tid] + sh_q[256 + tid] + sh_q[512 + tid] + sh_q[768 + tid];
    atomicAdd(&g_bn[tid], ts);
    atomicAdd(&g_bn[256 + tid], tq);
}

// ---------------- layer-2: BN-finalize prologue + BN+ELU + tf32 GEMM ----------------
#define SA2 36
#define SB2 88
__global__ __launch_bounds__(256) void k_gemm2_tc(
    const float* __restrict__ gamma, const float* __restrict__ beta,
    float* __restrict__ xl2, float* __restrict__ xr2, int M)
{
    __shared__ uint32_t As2[64 * SA2];
    __shared__ uint32_t Bs2[32 * SB2];
    __shared__ float sh_bns[256];
    __shared__ float sh_bnt[256];
    int tid = threadIdx.x;
    int lane = tid & 31, wid = tid >> 5;
    int warp_m = wid & 3, warp_n = wid >> 2;
    int m0 = blockIdx.x * 64;
    float acc[5][4] = {};

    {
        float invN = 1.f / (float)M;
        float mu = g_bn[tid] * invN;
        float var = g_bn[256 + tid] * invN - mu * mu;
        float rs = rsqrtf(var + 1e-5f);
        float s = gamma[tid] * rs;
        sh_bns[tid] = s;
        sh_bnt[tid] = beta[tid] - s * mu;
    }
    __syncthreads();

    for (int k0 = 0; k0 < 256; k0 += 32) {
#pragma unroll
        for (int i = 0; i < 2; i++) {
            int f = tid + i * 256;
            int r = f >> 3, c4 = (f & 7) * 4;
            int gr = m0 + r;
            float4 v = make_float4(0.f, 0.f, 0.f, 0.f);
            if (gr < M) v = *(const float4*)&g_h1[(size_t)gr * 256 + k0 + c4];
            float4 s4 = *(const float4*)&sh_bns[k0 + c4];
            float4 t4 = *(const float4*)&sh_bnt[k0 + c4];
            float e0 = s4.x * v.x + t4.x; e0 = e0 > 0.f ? e0 : (__expf(e0) - 1.f);
            float e1 = s4.y * v.y + t4.y; e1 = e1 > 0.f ? e1 : (__expf(e1) - 1.f);
            float e2 = s4.z * v.z + t4.z; e2 = e2 > 0.f ? e2 : (__expf(e2) - 1.f);
            float e3 = s4.w * v.w + t4.w; e3 = e3 > 0.f ? e3 : (__expf(e3) - 1.f);
            uint4 u = make_uint4(f2tf32(e0), f2tf32(e1), f2tf32(e2), f2tf32(e3));
            *(uint4*)&As2[r * SA2 + c4] = u;
        }
#pragma unroll
        for (int i = 0; i < 3; i++) {
            int f = tid + i * 256;
            if (f < 640) {
                int k = f / 20, n4 = (f % 20) * 4;
                *(uint4*)&Bs2[k * SB2 + n4] =
                    *(const uint4*)&g_W2t[(size_t)(k0 + k) * 80 + n4];
            }
        }
        __syncthreads();
#pragma unroll
        for (int ks = 0; ks < 4; ks++) {
            int kc = ks * 8 + (lane & 3);
            int r = warp_m * 16 + (lane >> 2);
            uint32_t a[4];
            a[0] = As2[r * SA2 + kc];
            a[1] = As2[(r + 8) * SA2 + kc];
            a[2] = As2[r * SA2 + kc + 4];
            a[3] = As2[(r + 8) * SA2 + kc + 4];
#pragma unroll
            for (int nj = 0; nj < 5; nj++) {
                int n = warp_n * 40 + nj * 8 + (lane >> 2);
                uint32_t b0 = Bs2[kc * SB2 + n];
                uint32_t b1 = Bs2[(kc + 4) * SB2 + n];
                mma_tf32(acc[nj], a, b0, b1);
            }
        }
        __syncthreads();
    }

    float* O = warp_n ? xr2 : xl2;
    int r = m0 + warp_m * 16 + (lane >> 2);
#pragma unroll
    for (int nj = 0; nj < 5; nj++) {
        int cc = nj * 8 + (lane & 3) * 2;
        if (r < M)
            *(float2*)&O[(size_t)r * 40 + cc] = make_float2(acc[nj][0], acc[nj][1]);
        if (r + 8 < M)
            *(float2*)&O[(size_t)(r + 8) * 40 + cc] = make_float2(acc[nj][2], acc[nj][3]);
    }
}

// ---------------- layer-2 fused single-pass online-softmax attention ----------------
__global__ __launch_bounds__(256) void k_attn2(const float* __restrict__ att2,
                                               const float* __restrict__ b2,
                                               float* __restrict__ out, int N)
{
    // reset BN accumulators for the next graph replay (gemm2 already consumed them)
    if (blockIdx.x == 0) {
        g_bn[threadIdx.x] = 0.f;
        g_bn[256 + threadIdx.x] = 0.f;
    }

    int gt = blockIdx.x * blockDim.x + threadIdx.x;
    int w = gt >> 5, lane = gt & 31;
    if (w >= N) return;
    int beg = g_offs[w], end = g_offs[w + 1];
    int sub = lane >> 3, l8 = lane & 7;

    float xr[5], at[5];
#pragma unroll
    for (int j = 0; j < 5; j++) {
        int c = l8 * 5 + j;
        xr[j] = g_xr2[(size_t)w * 40 + c];
        at[j] = att2[c];
    }

    float mx = -1e30f, dn = 0.f;
    float acc[5] = {};

    for (int p0 = beg; p0 < end; p0 += 4) {
        int p = p0 + sub;
        bool valid = (p < end);
        int src = g_src[valid ? p : beg];
        float xls[5];
        float s = 0.f;
#pragma unroll
        for (int j = 0; j < 5; j++) {
            xls[j] = g_xl2[(size_t)src * 40 + l8 * 5 + j];
            float v = xls[j] + xr[j];
            s += fmaxf(v, 0.2f * v) * at[j];
        }
        s += __shfl_xor_sync(0xffffffffu, s, 4);
        s += __shfl_xor_sync(0xffffffffu, s, 2);
        s += __shfl_xor_sync(0xffffffffu, s, 1);
        if (!valid) s = -1e30f;
        float mnew = fmaxf(mx, s);
        float sc = __expf(mx - mnew);
        float a  = valid ? __expf(s - mnew) : 0.f;
        dn = dn * sc + a;
#pragma unroll
        for (int j = 0; j < 5; j++) acc[j] = acc[j] * sc + a * xls[j];
        mx = mnew;
    }

#pragma unroll
    for (int off = 8; off <= 16; off <<= 1) {
        float mo  = __shfl_xor_sync(0xffffffffu, mx, off);
        float dno = __shfl_xor_sync(0xffffffffu, dn, off);
        float ao[5];
#pragma unroll
        for (int j = 0; j < 5; j++) ao[j] = __shfl_xor_sync(0xffffffffu, acc[j], off);
        float m = fmaxf(mx, mo);
        float f1 = __expf(mx - m), f2 = __expf(mo - m);
        dn = dn * f1 + dno * f2;
#pragma unroll
        for (int j = 0; j < 5; j++) acc[j] = acc[j] * f1 + ao[j] * f2;
        mx = m;
    }

    float inv = 1.f / (dn + 1e-16f);
    if (sub == 0) {
#pragma unroll
        for (int j = 0; j < 5; j++) {
            int c = l8 * 5 + j;
            out[(size_t)w * 40 + c] = acc[j] * inv + b2[c];
        }
    }
}

// ---------------- host launcher (single stream) ----------------
extern "C" void kernel_launch(void* const* d_in, const int* in_sizes, int n_in,
                              void* d_out, int out_size)
{
    const float* x      = (const float*)d_in[0];
    const int*   ei     = (const int*)  d_in[1];
    const float* Wl1    = (const float*)d_in[2];
    const float* Wr1    = (const float*)d_in[3];
    const float* att1   = (const float*)d_in[4];
    const float* b1     = (const float*)d_in[5];
    const float* gamma1 = (const float*)d_in[6];
    const float* beta1  = (const float*)d_in[7];
    const float* Wl2    = (const float*)d_in[8];
    const float* Wr2    = (const float*)d_in[9];
    const float* att2   = (const float*)d_in[10];
    const float* b2     = (const float*)d_in[11];
    float* out = (float*)d_out;

    int N = in_sizes[0] / 128;
    int E = in_sizes[1] / 2;
    int ET = E + N;
    int G = (ET + 3) / 4;

    void *pxl1, *pxr1, *pxl2, *pxr2;
    cudaGetSymbolAddress(&pxl1, g_xl1);
    cudaGetSymbolAddress(&pxr1, g_xr1);
    cudaGetSymbolAddress(&pxl2, g_xl2);
    cudaGetSymbolAddress(&pxr2, g_xr2);

    int CB  = (G + 255) / 256;
    int W1B = (128 * 512) / 256;
    int W2B = (256 * 80 + 255) / 256;
    int XB  = (N * 32 + 255) / 256;
    int PRE = CB + W1B + W2B + XB;

    k_pre<<<PRE, 256>>>(ei, E, N, G, CB, W1B, W2B, x, Wl1, Wr1, Wl2, Wr2);
    k_scan<<<1, 1024>>>(N);

    int FB = (G + 511) / 512;
    int GB = 4 * ((N + 127) / 128);
    k_fill_gemm1<<<FB + GB, 512>>>(ei, E, N, G, FB, (float*)pxl1, (float*)pxr1, N);

    k_attn1<<<(N + 7) / 8, 256>>>(att1, b1, N);

    k_bnstats<<<(N + 127) / 128, 256>>>(N);

    k_gemm2_tc<<<(N + 63) / 64, 256>>>(gamma1, beta1, (float*)pxl2, (float*)pxr2, N);

    k_attn2<<<(N + 7) / 8, 256>>>(att2, b2, out, N);
}

// round 15
// speedup vs baseline: 1.0013x; 1.0013x over previous
#include <cuda_runtime.h>
#include <math.h>
#include <stdint.h>

#define D1 256
#define C2 40
#define MAXN 50176
#define MAXE 800000
#define MAXET (MAXE + MAXN)

// ---------------- static scratch (no runtime allocation) ----------------
__device__ float    g_xl1[(size_t)MAXN * D1];
__device__ float    g_xr1[(size_t)MAXN * D1];
__device__ float    g_h1 [(size_t)MAXN * D1];
__device__ float    g_xl2[(size_t)MAXN * C2];
__device__ float    g_xr2[(size_t)MAXN * C2];
__device__ uint32_t g_xt [(size_t)MAXN * 128];   // x pre-converted to tf32
__device__ int      g_counts[MAXN + 1];          // zero-init; re-zeroed by attn1 each run
__device__ int      g_offs  [MAXN + 1];
__device__ int      g_cursor[MAXN + 1];
__device__ int      g_src[MAXET];
__device__ float    g_bn[512];                   // zero-init; re-zeroed by attn2 each run
__device__ uint32_t g_W1t[128 * 512];   // [Wl1 | Wr1] tf32
__device__ uint32_t g_W2t[256 * 80];    // [Wl2 | Wr2] tf32

__device__ __forceinline__ uint32_t f2tf32(float f) {
    uint32_t r;
    asm("cvt.rna.tf32.f32 %0, %1;" : "=r"(r) : "f"(f));
    return r;
}

__device__ __forceinline__ void mma_tf32(float c[4], const uint32_t a[4],
                                         uint32_t b0, uint32_t b1) {
    asm volatile(
        "mma.sync.aligned.m16n8k8.row.col.f32.tf32.tf32.f32 "
        "{%0,%1,%2,%3}, {%4,%5,%6,%7}, {%8,%9}, {%0,%1,%2,%3};"
        : "+f"(c[0]), "+f"(c[1]), "+f"(c[2]), "+f"(c[3])
        : "r"(a[0]), "r"(a[1]), "r"(a[2]), "r"(a[3]), "r"(b0), "r"(b1));
}

__device__ __forceinline__ void cp_async16(uint32_t smem_addr, const void* gptr) {
    asm volatile("cp.async.cg.shared.global [%0], [%1], 16;"
                 :: "r"(smem_addr), "l"(gptr));
}

// ---------------- fused pre-pass: count | w1cat | w2cat | x-convert ----------------
__global__ void k_pre(const int* __restrict__ ei, int E, int N, int G,
                      int CB, int W1B, int W2B,
                      const float* __restrict__ x,
                      const float* __restrict__ Wl1, const float* __restrict__ Wr1,
                      const float* __restrict__ Wl2, const float* __restrict__ Wr2)
{
    int b = blockIdx.x, tid = threadIdx.x;
    if (b < CB) {
        int t = b * 256 + tid;
        if (t >= G) return;
        int ET = E + N;
#pragma unroll
        for (int q = 0; q < 4; q++) {
            int i = t + q * G;
            if (i < ET) {
                int dst = (i < E) ? ei[E + i] : (i - E);
                atomicAdd(&g_counts[dst], 1);
            }
        }
    } else if (b < CB + W1B) {
        int i = (b - CB) * 256 + tid;
        int k = i >> 9, c = i & 511;
        float v = (c < 256) ? Wl1[k * 256 + c] : Wr1[k * 256 + (c - 256)];
        g_W1t[i] = f2tf32(v);
    } else if (b < CB + W1B + W2B) {
        int i = (b - CB - W1B) * 256 + tid;
        if (i < 256 * 80) {
            int k = i / 80, c = i % 80;
            float v = (c < 40) ? Wl2[k * 40 + c] : Wr2[k * 40 + (c - 40)];
            g_W2t[i] = f2tf32(v);
        }
    } else {
        int i = (b - CB - W1B - W2B) * 256 + tid;
        if (i < N * 32) {
            float4 v = ((const float4*)x)[i];
            ((uint4*)g_xt)[i] = make_uint4(f2tf32(v.x), f2tf32(v.y),
                                           f2tf32(v.z), f2tf32(v.w));
        }
    }
}

// ---------------- scan: 4 elements per thread ----------------
__global__ void k_scan(int n) {
    __shared__ int wsum[32];
    __shared__ int s_carry;
    int t = threadIdx.x, lane = t & 31, w = t >> 5;
    if (t == 0) s_carry = 0;
    __syncthreads();
    for (int base = 0; base < n; base += 4096) {
        int i0 = base + t * 4;
        int v0 = (i0 + 0 < n) ? g_counts[i0 + 0] : 0;
        int v1 = (i0 + 1 < n) ? g_counts[i0 + 1] : 0;
        int v2 = (i0 + 2 < n) ? g_counts[i0 + 2] : 0;
        int v3 = (i0 + 3 < n) ? g_counts[i0 + 3] : 0;
        int sum4 = v0 + v1 + v2 + v3;
        int s = sum4;
#pragma unroll
        for (int o = 1; o < 32; o <<= 1) {
            int y = __shfl_up_sync(0xffffffffu, s, o);
            if (lane >= o) s += y;
        }
        if (lane == 31) wsum[w] = s;
        __syncthreads();
        if (w == 0) {
            int ws = wsum[lane];
#pragma unroll
            for (int o = 1; o < 32; o <<= 1) {
                int y = __shfl_up_sync(0xffffffffu, ws, o);
                if (lane >= o) ws += y;
            }
            wsum[lane] = ws;
        }
        __syncthreads();
        int excl = s_carry + (w > 0 ? wsum[w - 1] : 0) + (s - sum4);
        if (i0 + 0 < n) { g_offs[i0 + 0] = excl;           g_cursor[i0 + 0] = excl; }
        if (i0 + 1 < n) { g_offs[i0 + 1] = excl + v0;      g_cursor[i0 + 1] = excl + v0; }
        if (i0 + 2 < n) { g_offs[i0 + 2] = excl + v0 + v1; g_cursor[i0 + 2] = excl + v0 + v1; }
        if (i0 + 3 < n) { g_offs[i0 + 3] = excl + v0 + v1 + v2;
                          g_cursor[i0 + 3] = excl + v0 + v1 + v2; }
        int total = wsum[31];
        __syncthreads();
        if (t == 0) s_carry += total;
        __syncthreads();
    }
    if (t == 0) g_offs[n] = s_carry;
}

// ---------------- fused: CSR fill | layer-1 tf32 GEMM (cp.async double buffer) ----------------
#define KC 16
#define SAW 20
#define SBW 136
__global__ __launch_bounds__(512, 2) void k_fill_gemm1(
    const int* __restrict__ ei, int E, int N, int G, int FB,
    float* __restrict__ outL, float* __restrict__ outR, int M)
{
    __shared__ uint32_t As[2][128 * SAW];
    __shared__ uint32_t Bs[2][KC * SBW];
    int tid = threadIdx.x;

    if (blockIdx.x < FB) {              // ---- CSR fill ----
        int t = blockIdx.x * 512 + tid;
        if (t >= G) return;
        int ET = E + N;
#pragma unroll
        for (int q = 0; q < 4; q++) {
            int i = t + q * G;
            if (i < ET) {
                int src, dst;
                if (i < E) { src = ei[i]; dst = ei[E + i]; } else { src = dst = i - E; }
                int p = atomicAdd(&g_cursor[dst], 1);
                g_src[p] = src;
            }
        }
        return;
    }

    // ---- GEMM: C[M,512] = xt[M,128] @ W1t[128,512] ----
    int flat = blockIdx.x - FB;
    int n0 = (flat & 3) << 7;
    int m0 = (flat >> 2) << 7;
    int lane = tid & 31, wid = tid >> 5;
    int warp_m = wid >> 2, warp_n = wid & 3;
    float acc[2][4][4] = {};

    int ar = tid >> 2, aq = (tid & 3) * 4;
    int bk = tid >> 5, bc = (tid & 31) * 4;
    const uint32_t* gA = &g_xt[(size_t)(m0 + ar) * 128 + aq];
    const uint32_t* gB = &g_W1t[(size_t)bk * 512 + n0 + bc];

    uint32_t sA0 = (uint32_t)__cvta_generic_to_shared(&As[0][ar * SAW + aq]);
    uint32_t sA1 = (uint32_t)__cvta_generic_to_shared(&As[1][ar * SAW + aq]);
    uint32_t sB0 = (uint32_t)__cvta_generic_to_shared(&Bs[0][bk * SBW + bc]);
    uint32_t sB1 = (uint32_t)__cvta_generic_to_shared(&Bs[1][bk * SBW + bc]);

    cp_async16(sA0, gA);
    cp_async16(sB0, gB);
    asm volatile("cp.async.commit_group;");

#pragma unroll
    for (int it = 0; it < 8; it++) {
        int buf = it & 1;
        if (it < 7) {
            int k0 = (it + 1) * KC;
            cp_async16(buf ? sA0 : sA1, gA + k0);
            cp_async16(buf ? sB0 : sB1, gB + (size_t)k0 * 512);
            asm volatile("cp.async.commit_group;");
            asm volatile("cp.async.wait_group 1;");
        } else {
            asm volatile("cp.async.wait_group 0;");
        }
        __syncthreads();

        const uint32_t* Ab = As[buf];
        const uint32_t* Bb = Bs[buf];
#pragma unroll
        for (int ks = 0; ks < 2; ks++) {
            int kc = ks * 8 + (lane & 3);
            uint32_t a[2][4];
            int r0 = warp_m * 32 + (lane >> 2);
#pragma unroll
            for (int mi = 0; mi < 2; mi++) {
                int r = r0 + mi * 16;
                a[mi][0] = Ab[r * SAW + kc];
                a[mi][1] = Ab[(r + 8) * SAW + kc];
                a[mi][2] = Ab[r * SAW + kc + 4];
                a[mi][3] = Ab[(r + 8) * SAW + kc + 4];
            }
#pragma unroll
            for (int nj = 0; nj < 4; nj++) {
                int n = warp_n * 32 + nj * 8 + (lane >> 2);
                uint32_t b0 = Bb[kc * SBW + n];
                uint32_t b1 = Bb[(kc + 4) * SBW + n];
                mma_tf32(acc[0][nj], a[0], b0, b1);
                mma_tf32(acc[1][nj], a[1], b0, b1);
            }
        }
        __syncthreads();
    }

    float* O = (n0 < 256) ? outL : outR;
    int nb = n0 & 255;
#pragma unroll
    for (int mi = 0; mi < 2; mi++) {
        int r = m0 + warp_m * 32 + mi * 16 + (lane >> 2);
#pragma unroll
        for (int nj = 0; nj < 4; nj++) {
            int nc = nb + warp_n * 32 + nj * 8 + (lane & 3) * 2;
            if (r < M)
                *(float2*)&O[(size_t)r * 256 + nc] =
                    make_float2(acc[mi][nj][0], acc[mi][nj][1]);
            if (r + 8 < M)
                *(float2*)&O[(size_t)(r + 8) * 256 + nc] =
                    make_float2(acc[mi][nj][2], acc[mi][nj][3]);
        }
    }
}

// ---------------- layer-1 attention: 2 warps per node, split online softmax ----------------
// block = 256 thr = 8 warps = 4 nodes; warp pair (half 0/1) splits the edge list,
// warp 1 publishes partials via smem, warp 0 merges + writes. Barrier is unconditional.
#define SH11 11
__global__ __launch_bounds__(256) void k_attn1(const float* __restrict__ att,
                                               const float* __restrict__ b1, int N)
{
    __shared__ float sh[4 * 32 * SH11];
    int tid = threadIdx.x, wid = tid >> 5, lane = tid & 31;
    int slot = wid >> 1, half = wid & 1;
    int w = blockIdx.x * 4 + slot;
    int wc = (w < N) ? w : (N - 1);          // safe index for loads

    int beg = g_offs[wc], end = g_offs[wc + 1];
    int len = end - beg;
    int mid = beg + ((len + 1) >> 1);
    int lo = half ? mid : beg;
    int hi = half ? end : mid;

    const float4* pxr = (const float4*)g_xr1 + (size_t)wc * 64 + lane * 2;
    float4 r0 = pxr[0], r1 = pxr[1];
    const float4* pa = (const float4*)att + lane * 2;
    float4 at0 = pa[0], at1 = pa[1];

    float mx = -1e30f, dn = 0.f;
    float c0 = 0, c1 = 0, c2 = 0, c3 = 0, c4 = 0, c5 = 0, c6 = 0, c7 = 0;

    int p = lo;
    for (; p + 2 <= hi; p += 2) {
        int s0i = g_src[p], s1i = g_src[p + 1];
        const float4* p0 = (const float4*)g_xl1 + (size_t)s0i * 64 + lane * 2;
        const float4* p1 = (const float4*)g_xl1 + (size_t)s1i * 64 + lane * 2;
        float4 x0 = p0[0], x1 = p0[1];
        float4 y0 = p1[0], y1 = p1[1];
        float v, s0 = 0.f, s1 = 0.f;
        v = x0.x + r0.x; s0 += fmaxf(v, 0.2f * v) * at0.x;
        v = x0.y + r0.y; s0 += fmaxf(v, 0.2f * v) * at0.y;
        v = x0.z + r0.z; s0 += fmaxf(v, 0.2f * v) * at0.z;
        v = x0.w + r0.w; s0 += fmaxf(v, 0.2f * v) * at0.w;
        v = x1.x + r1.x; s0 += fmaxf(v, 0.2f * v) * at1.x;
        v = x1.y + r1.y; s0 += fmaxf(v, 0.2f * v) * at1.y;
        v = x1.z + r1.z; s0 += fmaxf(v, 0.2f * v) * at1.z;
        v = x1.w + r1.w; s0 += fmaxf(v, 0.2f * v) * at1.w;
        v = y0.x + r0.x; s1 += fmaxf(v, 0.2f * v) * at0.x;
        v = y0.y + r0.y; s1 += fmaxf(v, 0.2f * v) * at0.y;
        v = y0.z + r0.z; s1 += fmaxf(v, 0.2f * v) * at0.z;
        v = y0.w + r0.w; s1 += fmaxf(v, 0.2f * v) * at0.w;
        v = y1.x + r1.x; s1 += fmaxf(v, 0.2f * v) * at1.x;
        v = y1.y + r1.y; s1 += fmaxf(v, 0.2f * v) * at1.y;
        v = y1.z + r1.z; s1 += fmaxf(v, 0.2f * v) * at1.z;
        v = y1.w + r1.w; s1 += fmaxf(v, 0.2f * v) * at1.w;
        s0 += __shfl_xor_sync(0xffffffffu, s0, 4);
        s1 += __shfl_xor_sync(0xffffffffu, s1, 4);
        s0 += __shfl_xor_sync(0xffffffffu, s0, 2);
        s1 += __shfl_xor_sync(0xffffffffu, s1, 2);
        s0 += __shfl_xor_sync(0xffffffffu, s0, 1);
        s1 += __shfl_xor_sync(0xffffffffu, s1, 1);
        float mnew = fmaxf(mx, fmaxf(s0, s1));
        float sc = __expf(mx - mnew);
        float e0 = __expf(s0 - mnew);
        float e1 = __expf(s1 - mnew);
        dn = dn * sc + e0 + e1;
        c0 = c0 * sc + e0 * x0.x + e1 * y0.x;
        c1 = c1 * sc + e0 * x0.y + e1 * y0.y;
        c2 = c2 * sc + e0 * x0.z + e1 * y0.z;
        c3 = c3 * sc + e0 * x0.w + e1 * y0.w;
        c4 = c4 * sc + e0 * x1.x + e1 * y1.x;
        c5 = c5 * sc + e0 * x1.y + e1 * y1.y;
        c6 = c6 * sc + e0 * x1.z + e1 * y1.z;
        c7 = c7 * sc + e0 * x1.w + e1 * y1.w;
        mx = mnew;
    }
    if (p < hi) {
        int src = g_src[p];
        const float4* pl = (const float4*)g_xl1 + (size_t)src * 64 + lane * 2;
        float4 a0 = pl[0], a1 = pl[1];
        float v, s = 0.f;
        v = a0.x + r0.x; s += fmaxf(v, 0.2f * v) * at0.x;
        v = a0.y + r0.y; s += fmaxf(v, 0.2f * v) * at0.y;
        v = a0.z + r0.z; s += fmaxf(v, 0.2f * v) * at0.z;
        v = a0.w + r0.w; s += fmaxf(v, 0.2f * v) * at0.w;
        v = a1.x + r1.x; s += fmaxf(v, 0.2f * v) * at1.x;
        v = a1.y + r1.y; s += fmaxf(v, 0.2f * v) * at1.y;
        v = a1.z + r1.z; s += fmaxf(v, 0.2f * v) * at1.z;
        v = a1.w + r1.w; s += fmaxf(v, 0.2f * v) * at1.w;
        s += __shfl_xor_sync(0xffffffffu, s, 4);
        s += __shfl_xor_sync(0xffffffffu, s, 2);
        s += __shfl_xor_sync(0xffffffffu, s, 1);
        float mnew = fmaxf(mx, s);
        float sc = __expf(mx - mnew);
        float a = __expf(s - mnew);
        dn = dn * sc + a;
        c0 = c0 * sc + a * a0.x; c1 = c1 * sc + a * a0.y;
        c2 = c2 * sc + a * a0.z; c3 = c3 * sc + a * a0.w;
        c4 = c4 * sc + a * a1.x; c5 = c5 * sc + a * a1.y;
        c6 = c6 * sc + a * a1.z; c7 = c7 * sc + a * a1.w;
        mx = mnew;
    }

    float* shl = &sh[(slot * 32 + lane) * SH11];
    if (half == 1) {
        shl[0] = mx; shl[1] = dn;
        shl[2] = c0; shl[3] = c1; shl[4] = c2; shl[5] = c3;
        shl[6] = c4; shl[7] = c5; shl[8] = c6; shl[9] = c7;
    }
    __syncthreads();
    if (half == 0 && w < N) {
        float mo = shl[0], dno = shl[1];
        float m = fmaxf(mx, mo);
        float fA = __expf(mx - m), fB = __expf(mo - m);
        dn = dn * fA + dno * fB;
        c0 = c0 * fA + shl[2] * fB; c1 = c1 * fA + shl[3] * fB;
        c2 = c2 * fA + shl[4] * fB; c3 = c3 * fA + shl[5] * fB;
        c4 = c4 * fA + shl[6] * fB; c5 = c5 * fA + shl[7] * fB;
        c6 = c6 * fA + shl[8] * fB; c7 = c7 * fA + shl[9] * fB;
        float inv = 1.f / (dn + 1e-16f);
        const float4* pb = (const float4*)b1 + lane * 2;
        float4 bb0 = pb[0], bb1 = pb[1];
        ((float4*)g_h1)[(size_t)w * 64 + lane * 2 + 0] =
            make_float4(c0 * inv + bb0.x, c1 * inv + bb0.y,
                        c2 * inv + bb0.z, c3 * inv + bb0.w);
        ((float4*)g_h1)[(size_t)w * 64 + lane * 2 + 1] =
            make_float4(c4 * inv + bb1.x, c5 * inv + bb1.y,
                        c6 * inv + bb1.z, c7 * inv + bb1.w);
        if (lane == 0) g_counts[w] = 0;      // reset for next replay
    }
}

// ---------------- batch-norm stats (float4, 64 quads x 4 row-groups) ----------------
__global__ __launch_bounds__(256) void k_bnstats(int N)
{
    __shared__ float sh_s[4 * 256];
    __shared__ float sh_q[4 * 256];
    int tid = threadIdx.x;
    int quad = tid & 63, rg = tid >> 6;
    int c4 = quad * 4;
    int rend = min(blockIdx.x * 128 + 128, N);
    float4 s = make_float4(0.f, 0.f, 0.f, 0.f);
    float4 q = make_float4(0.f, 0.f, 0.f, 0.f);
    for (int r = blockIdx.x * 128 + rg; r < rend; r += 4) {
        float4 v = *(const float4*)&g_h1[(size_t)r * 256 + c4];
        s.x += v.x; s.y += v.y; s.z += v.z; s.w += v.w;
        q.x += v.x * v.x; q.y += v.y * v.y; q.z += v.z * v.z; q.w += v.w * v.w;
    }
    *(float4*)&sh_s[rg * 256 + c4] = s;
    *(float4*)&sh_q[rg * 256 + c4] = q;
    __syncthreads();
    float ts = sh_s[tid] + sh_s[256 + tid] + sh_s[512 + tid] + sh_s[768 + tid];
    float tq = sh_q[tid] + sh_q[256 + tid] + sh_q[512 + tid] + sh_q[768 + tid];
    atomicAdd(&g_bn[tid], ts);
    atomicAdd(&g_bn[256 + tid], tq);
}

// ---------------- layer-2: BN-finalize prologue + BN+ELU + tf32 GEMM ----------------
#define SA2 36
#define SB2 88
__global__ __launch_bounds__(256) void k_gemm2_tc(
    const float* __restrict__ gamma, const float* __restrict__ beta,
    float* __restrict__ xl2, float* __restrict__ xr2, int M)
{
    __shared__ uint32_t As2[64 * SA2];
    __shared__ uint32_t Bs2[32 * SB2];
    __shared__ float sh_bns[256];
    __shared__ float sh_bnt[256];
    int tid = threadIdx.x;
    int lane = tid & 31, wid = tid >> 5;
    int warp_m = wid & 3, warp_n = wid >> 2;
    int m0 = blockIdx.x * 64;
    float acc[5][4] = {};

    {
        float invN = 1.f / (float)M;
        float mu = g_bn[tid] * invN;
        float var = g_bn[256 + tid] * invN - mu * mu;
        float rs = rsqrtf(var + 1e-5f);
        float s = gamma[tid] * rs;
        sh_bns[tid] = s;
        sh_bnt[tid] = beta[tid] - s * mu;
    }
    __syncthreads();

    for (int k0 = 0; k0 < 256; k0 += 32) {
#pragma unroll
        for (int i = 0; i < 2; i++) {
            int f = tid + i * 256;
            int r = f >> 3, c4 = (f & 7) * 4;
            int gr = m0 + r;
            float4 v = make_float4(0.f, 0.f, 0.f, 0.f);
            if (gr < M) v = *(const float4*)&g_h1[(size_t)gr * 256 + k0 + c4];
            float4 s4 = *(const float4*)&sh_bns[k0 + c4];
            float4 t4 = *(const float4*)&sh_bnt[k0 + c4];
            float e0 = s4.x * v.x + t4.x; e0 = e0 > 0.f ? e0 : (__expf(e0) - 1.f);
            float e1 = s4.y * v.y + t4.y; e1 = e1 > 0.f ? e1 : (__expf(e1) - 1.f);
            float e2 = s4.z * v.z + t4.z; e2 = e2 > 0.f ? e2 : (__expf(e2) - 1.f);
            float e3 = s4.w * v.w + t4.w; e3 = e3 > 0.f ? e3 : (__expf(e3) - 1.f);
            uint4 u = make_uint4(f2tf32(e0), f2tf32(e1), f2tf32(e2), f2tf32(e3));
            *(uint4*)&As2[r * SA2 + c4] = u;
        }
#pragma unroll
        for (int i = 0; i < 3; i++) {
            int f = tid + i * 256;
            if (f < 640) {
                int k = f / 20, n4 = (f % 20) * 4;
                *(uint4*)&Bs2[k * SB2 + n4] =
                    *(const uint4*)&g_W2t[(size_t)(k0 + k) * 80 + n4];
            }
        }
        __syncthreads();
#pragma unroll
        for (int ks = 0; ks < 4; ks++) {
            int kc = ks * 8 + (lane & 3);
            int r = warp_m * 16 + (lane >> 2);
            uint32_t a[4];
            a[0] = As2[r * SA2 + kc];
            a[1] = As2[(r + 8) * SA2 + kc];
            a[2] = As2[r * SA2 + kc + 4];
            a[3] = As2[(r + 8) * SA2 + kc + 4];
#pragma unroll
            for (int nj = 0; nj < 5; nj++) {
                int n = warp_n * 40 + nj * 8 + (lane >> 2);
                uint32_t b0 = Bs2[kc * SB2 + n];
                uint32_t b1 = Bs2[(kc + 4) * SB2 + n];
                mma_tf32(acc[nj], a, b0, b1);
            }
        }
        __syncthreads();
    }

    float* O = warp_n ? xr2 : xl2;
    int r = m0 + warp_m * 16 + (lane >> 2);
#pragma unroll
    for (int nj = 0; nj < 5; nj++) {
        int cc = nj * 8 + (lane & 3) * 2;
        if (r < M)
            *(float2*)&O[(size_t)r * 40 + cc] = make_float2(acc[nj][0], acc[nj][1]);
        if (r + 8 < M)
            *(float2*)&O[(size_t)(r + 8) * 40 + cc] = make_float2(acc[nj][2], acc[nj][3]);
    }
}

// ---------------- layer-2 fused single-pass online-softmax attention ----------------
__global__ __launch_bounds__(256) void k_attn2(const float* __restrict__ att2,
                                               const float* __restrict__ b2,
                                               float* __restrict__ out, int N)
{
    if (blockIdx.x == 0) {
        g_bn[threadIdx.x] = 0.f;
        g_bn[256 + threadIdx.x] = 0.f;
    }

    int gt = blockIdx.x * blockDim.x + threadIdx.x;
    int w = gt >> 5, lane = gt & 31;
    if (w >= N) return;
    int beg = g_offs[w], end = g_offs[w + 1];
    int sub = lane >> 3, l8 = lane & 7;

    float xr[5], at[5];
#pragma unroll
    for (int j = 0; j < 5; j++) {
        int c = l8 * 5 + j;
        xr[j] = g_xr2[(size_t)w * 40 + c];
        at[j] = att2[c];
    }

    float mx = -1e30f, dn = 0.f;
    float acc[5] = {};

    for (int p0 = beg; p0 < end; p0 += 4) {
        int p = p0 + sub;
        bool valid = (p < end);
        int src = g_src[valid ? p : beg];
        float xls[5];
        float s = 0.f;
#pragma unroll
        for (int j = 0; j < 5; j++) {
            xls[j] = g_xl2[(size_t)src * 40 + l8 * 5 + j];
            float v = xls[j] + xr[j];
            s += fmaxf(v, 0.2f * v) * at[j];
        }
        s += __shfl_xor_sync(0xffffffffu, s, 4);
        s += __shfl_xor_sync(0xffffffffu, s, 2);
        s += __shfl_xor_sync(0xffffffffu, s, 1);
        if (!valid) s = -1e30f;
        float mnew = fmaxf(mx, s);
        float sc = __expf(mx - mnew);
        float a  = valid ? __expf(s - mnew) : 0.f;
        dn = dn * sc + a;
#pragma unroll
        for (int j = 0; j < 5; j++) acc[j] = acc[j] * sc + a * xls[j];
        mx = mnew;
    }

#pragma unroll
    for (int off = 8; off <= 16; off <<= 1) {
        float mo  = __shfl_xor_sync(0xffffffffu, mx, off);
        float dno = __shfl_xor_sync(0xffffffffu, dn, off);
        float ao[5];
#pragma unroll
        for (int j = 0; j < 5; j++) ao[j] = __shfl_xor_sync(0xffffffffu, acc[j], off);
        float m = fmaxf(mx, mo);
        float f1 = __expf(mx - m), f2 = __expf(mo - m);
        dn = dn * f1 + dno * f2;
#pragma unroll
        for (int j = 0; j < 5; j++) acc[j] = acc[j] * f1 + ao[j] * f2;
        mx = m;
    }

    float inv = 1.f / (dn + 1e-16f);
    if (sub == 0) {
#pragma unroll
        for (int j = 0; j < 5; j++) {
            int c = l8 * 5 + j;
            out[(size_t)w * 40 + c] = acc[j] * inv + b2[c];
        }
    }
}

// ---------------- host launcher (single stream) ----------------
extern "C" void kernel_launch(void* const* d_in, const int* in_sizes, int n_in,
                              void* d_out, int out_size)
{
    const float* x      = (const float*)d_in[0];
    const int*   ei     = (const int*)  d_in[1];
    const float* Wl1    = (const float*)d_in[2];
    const float* Wr1    = (const float*)d_in[3];
    const float* att1   = (const float*)d_in[4];
    const float* b1     = (const float*)d_in[5];
    const float* gamma1 = (const float*)d_in[6];
    const float* beta1  = (const float*)d_in[7];
    const float* Wl2    = (const float*)d_in[8];
    const float* Wr2    = (const float*)d_in[9];
    const float* att2   = (const float*)d_in[10];
    const float* b2     = (const float*)d_in[11];
    float* out = (float*)d_out;

    int N = in_sizes[0] / 128;
    int E = in_sizes[1] / 2;
    int ET = E + N;
    int G = (ET + 3) / 4;

    void *pxl1, *pxr1, *pxl2, *pxr2;
    cudaGetSymbolAddress(&pxl1, g_xl1);
    cudaGetSymbolAddress(&pxr1, g_xr1);
    cudaGetSymbolAddress(&pxl2, g_xl2);
    cudaGetSymbolAddress(&pxr2, g_xr2);

    int CB  = (G + 255) / 256;
    int W1B = (128 * 512) / 256;
    int W2B = (256 * 80 + 255) / 256;
    int XB  = (N * 32 + 255) / 256;
    int PRE = CB + W1B + W2B + XB;

    k_pre<<<PRE, 256>>>(ei, E, N, G, CB, W1B, W2B, x, Wl1, Wr1, Wl2, Wr2);
    k_scan<<<1, 1024>>>(N);

    int FB = (G + 511) / 512;
    int GB = 4 * ((N + 127) / 128);
    k_fill_gemm1<<<FB + GB, 512>>>(ei, E, N, G, FB, (float*)pxl1, (float*)pxr1, N);

    k_attn1<<<(N + 3) / 4, 256>>>(att1, b1, N);

    k_bnstats<<<(N + 127) / 128, 256>>>(N);

    k_gemm2_tc<<<(N + 63) / 64, 256>>>(gamma1, beta1, (float*)pxl2, (float*)pxr2, N);

    k_attn2<<<(N + 7) / 8, 256>>>(att2, b2, out, N);
}

// round 17
// speedup vs baseline: 1.0710x; 1.0696x over previous
#include <cuda_runtime.h>
#include <math.h>
#include <stdint.h>

#define D1 256
#define C2 40
#define MAXN 50176
#define MAXE 800000
#define MAXET (MAXE + MAXN)

typedef unsigned long long U64;

// ---------------- static scratch (no runtime allocation) ----------------
__device__ float    g_xl1[(size_t)MAXN * D1];
__device__ float    g_xr1[(size_t)MAXN * D1];
__device__ float    g_h1 [(size_t)MAXN * D1];
__device__ float    g_xl2[(size_t)MAXN * C2];
__device__ float    g_xr2[(size_t)MAXN * C2];
__device__ uint32_t g_xt [(size_t)MAXN * 128];   // x pre-converted to tf32
__device__ int      g_counts[MAXN + 1];          // zero-init; re-zeroed by attn1 each run
__device__ int      g_offs  [MAXN + 1];
__device__ int      g_cursor[MAXN + 1];
__device__ int      g_src[MAXET];
__device__ float    g_bn[512];                   // zero-init; re-zeroed by attn2 each run
__device__ uint32_t g_W1t[128 * 512];   // [Wl1 | Wr1] tf32
__device__ uint32_t g_W2t[256 * 80];    // [Wl2 | Wr2] tf32

__device__ __forceinline__ uint32_t f2tf32(float f) {
    uint32_t r;
    asm("cvt.rna.tf32.f32 %0, %1;" : "=r"(r) : "f"(f));
    return r;
}

__device__ __forceinline__ void mma_tf32(float c[4], const uint32_t a[4],
                                         uint32_t b0, uint32_t b1) {
    asm volatile(
        "mma.sync.aligned.m16n8k8.row.col.f32.tf32.tf32.f32 "
        "{%0,%1,%2,%3}, {%4,%5,%6,%7}, {%8,%9}, {%0,%1,%2,%3};"
        : "+f"(c[0]), "+f"(c[1]), "+f"(c[2]), "+f"(c[3])
        : "r"(a[0]), "r"(a[1]), "r"(a[2]), "r"(a[3]), "r"(b0), "r"(b1));
}

__device__ __forceinline__ void cp_async16(uint32_t smem_addr, const void* gptr) {
    asm volatile("cp.async.cg.shared.global [%0], [%1], 16;"
                 :: "r"(smem_addr), "l"(gptr));
}

// ---- packed f32x2 helpers ----
__device__ __forceinline__ U64 add2(U64 a, U64 b) {
    U64 r; asm("add.rn.f32x2 %0,%1,%2;" : "=l"(r) : "l"(a), "l"(b)); return r;
}
__device__ __forceinline__ U64 mul2(U64 a, U64 b) {
    U64 r; asm("mul.rn.f32x2 %0,%1,%2;" : "=l"(r) : "l"(a), "l"(b)); return r;
}
__device__ __forceinline__ U64 fma2(U64 a, U64 b, U64 c) {
    U64 r; asm("fma.rn.f32x2 %0,%1,%2,%3;" : "=l"(r) : "l"(a), "l"(b), "l"(c)); return r;
}
__device__ __forceinline__ U64 abs2(U64 a) {
    U64 r; asm("and.b64 %0,%1,0x7FFFFFFF7FFFFFFF;" : "=l"(r) : "l"(a)); return r;
}
__device__ __forceinline__ U64 pack2(float x) {
    U64 r; asm("mov.b64 %0,{%1,%1};" : "=l"(r) : "f"(x)); return r;
}
__device__ __forceinline__ float2 unpack2(U64 a) {
    float lo, hi;
    asm("mov.b64 {%0,%1},%2;" : "=f"(lo), "=f"(hi) : "l"(a));
    return make_float2(lo, hi);
}

// ---------------- fused pre-pass: count | w1cat | w2cat | x-convert ----------------
__global__ void k_pre(const int* __restrict__ ei, int E, int N, int G,
                      int CB, int W1B, int W2B,
                      const float* __restrict__ x,
                      const float* __restrict__ Wl1, const float* __restrict__ Wr1,
                      const float* __restrict__ Wl2, const float* __restrict__ Wr2)
{
    int b = blockIdx.x, tid = threadIdx.x;
    if (b < CB) {
        int t = b * 256 + tid;
        if (t >= G) return;
        int ET = E + N;
#pragma unroll
        for (int q = 0; q < 4; q++) {
            int i = t + q * G;
            if (i < ET) {
                int dst = (i < E) ? ei[E + i] : (i - E);
                atomicAdd(&g_counts[dst], 1);
            }
        }
    } else if (b < CB + W1B) {
        int i = (b - CB) * 256 + tid;
        int k = i >> 9, c = i & 511;
        float v = (c < 256) ? Wl1[k * 256 + c] : Wr1[k * 256 + (c - 256)];
        g_W1t[i] = f2tf32(v);
    } else if (b < CB + W1B + W2B) {
        int i = (b - CB - W1B) * 256 + tid;
        if (i < 256 * 80) {
            int k = i / 80, c = i % 80;
            float v = (c < 40) ? Wl2[k * 40 + c] : Wr2[k * 40 + (c - 40)];
            g_W2t[i] = f2tf32(v);
        }
    } else {
        int i = (b - CB - W1B - W2B) * 256 + tid;
        if (i < N * 32) {
            float4 v = ((const float4*)x)[i];
            ((uint4*)g_xt)[i] = make_uint4(f2tf32(v.x), f2tf32(v.y),
                                           f2tf32(v.z), f2tf32(v.w));
        }
    }
}

// ---------------- scan: 4 elements per thread ----------------
__global__ void k_scan(int n) {
    __shared__ int wsum[32];
    __shared__ int s_carry;
    int t = threadIdx.x, lane = t & 31, w = t >> 5;
    if (t == 0) s_carry = 0;
    __syncthreads();
    for (int base = 0; base < n; base += 4096) {
        int i0 = base + t * 4;
        int v0 = (i0 + 0 < n) ? g_counts[i0 + 0] : 0;
        int v1 = (i0 + 1 < n) ? g_counts[i0 + 1] : 0;
        int v2 = (i0 + 2 < n) ? g_counts[i0 + 2] : 0;
        int v3 = (i0 + 3 < n) ? g_counts[i0 + 3] : 0;
        int sum4 = v0 + v1 + v2 + v3;
        int s = sum4;
#pragma unroll
        for (int o = 1; o < 32; o <<= 1) {
            int y = __shfl_up_sync(0xffffffffu, s, o);
            if (lane >= o) s += y;
        }
        if (lane == 31) wsum[w] = s;
        __syncthreads();
        if (w == 0) {
            int ws = wsum[lane];
#pragma unroll
            for (int o = 1; o < 32; o <<= 1) {
                int y = __shfl_up_sync(0xffffffffu, ws, o);
                if (lane >= o) ws += y;
            }
            wsum[lane] = ws;
        }
        __syncthreads();
        int excl = s_carry + (w > 0 ? wsum[w - 1] : 0) + (s - sum4);
        if (i0 + 0 < n) { g_offs[i0 + 0] = excl;           g_cursor[i0 + 0] = excl; }
        if (i0 + 1 < n) { g_offs[i0 + 1] = excl + v0;      g_cursor[i0 + 1] = excl + v0; }
        if (i0 + 2 < n) { g_offs[i0 + 2] = excl + v0 + v1; g_cursor[i0 + 2] = excl + v0 + v1; }
        if (i0 + 3 < n) { g_offs[i0 + 3] = excl + v0 + v1 + v2;
                          g_cursor[i0 + 3] = excl + v0 + v1 + v2; }
        int total = wsum[31];
        __syncthreads();
        if (t == 0) s_carry += total;
        __syncthreads();
    }
    if (t == 0) g_offs[n] = s_carry;
}

// ---------------- fused: CSR fill | layer-1 tf32 GEMM (cp.async double buffer) ----------------
#define KC 16
#define SAW 20
#define SBW 136
__global__ __launch_bounds__(512, 2) void k_fill_gemm1(
    const int* __restrict__ ei, int E, int N, int G, int FB,
    float* __restrict__ outL, float* __restrict__ outR, int M)
{
    __shared__ uint32_t As[2][128 * SAW];
    __shared__ uint32_t Bs[2][KC * SBW];
    int tid = threadIdx.x;

    if (blockIdx.x < FB) {              // ---- CSR fill ----
        int t = blockIdx.x * 512 + tid;
        if (t >= G) return;
        int ET = E + N;
#pragma unroll
        for (int q = 0; q < 4; q++) {
            int i = t + q * G;
            if (i < ET) {
                int src, dst;
                if (i < E) { src = ei[i]; dst = ei[E + i]; } else { src = dst = i - E; }
                int p = atomicAdd(&g_cursor[dst], 1);
                g_src[p] = src;
            }
        }
        return;
    }

    // ---- GEMM: C[M,512] = xt[M,128] @ W1t[128,512] ----
    int flat = blockIdx.x - FB;
    int n0 = (flat & 3) << 7;
    int m0 = (flat >> 2) << 7;
    int lane = tid & 31, wid = tid >> 5;
    int warp_m = wid >> 2, warp_n = wid & 3;
    float acc[2][4][4] = {};

    int ar = tid >> 2, aq = (tid & 3) * 4;
    int bk = tid >> 5, bc = (tid & 31) * 4;
    const uint32_t* gA = &g_xt[(size_t)(m0 + ar) * 128 + aq];
    const uint32_t* gB = &g_W1t[(size_t)bk * 512 + n0 + bc];

    uint32_t sA0 = (uint32_t)__cvta_generic_to_shared(&As[0][ar * SAW + aq]);
    uint32_t sA1 = (uint32_t)__cvta_generic_to_shared(&As[1][ar * SAW + aq]);
    uint32_t sB0 = (uint32_t)__cvta_generic_to_shared(&Bs[0][bk * SBW + bc]);
    uint32_t sB1 = (uint32_t)__cvta_generic_to_shared(&Bs[1][bk * SBW + bc]);

    cp_async16(sA0, gA);
    cp_async16(sB0, gB);
    asm volatile("cp.async.commit_group;");

#pragma unroll
    for (int it = 0; it < 8; it++) {
        int buf = it & 1;
        if (it < 7) {
            int k0 = (it + 1) * KC;
            cp_async16(buf ? sA0 : sA1, gA + k0);
            cp_async16(buf ? sB0 : sB1, gB + (size_t)k0 * 512);
            asm volatile("cp.async.commit_group;");
            asm volatile("cp.async.wait_group 1;");
        } else {
            asm volatile("cp.async.wait_group 0;");
        }
        __syncthreads();

        const uint32_t* Ab = As[buf];
        const uint32_t* Bb = Bs[buf];
#pragma unroll
        for (int ks = 0; ks < 2; ks++) {
            int kc = ks * 8 + (lane & 3);
            uint32_t a[2][4];
            int r0 = warp_m * 32 + (lane >> 2);
#pragma unroll
            for (int mi = 0; mi < 2; mi++) {
                int r = r0 + mi * 16;
                a[mi][0] = Ab[r * SAW + kc];
                a[mi][1] = Ab[(r + 8) * SAW + kc];
                a[mi][2] = Ab[r * SAW + kc + 4];
                a[mi][3] = Ab[(r + 8) * SAW + kc + 4];
            }
#pragma unroll
            for (int nj = 0; nj < 4; nj++) {
                int n = warp_n * 32 + nj * 8 + (lane >> 2);
                uint32_t b0 = Bb[kc * SBW + n];
                uint32_t b1 = Bb[(kc + 4) * SBW + n];
                mma_tf32(acc[0][nj], a[0], b0, b1);
                mma_tf32(acc[1][nj], a[1], b0, b1);
            }
        }
        __syncthreads();
    }

    float* O = (n0 < 256) ? outL : outR;
    int nb = n0 & 255;
#pragma unroll
    for (int mi = 0; mi < 2; mi++) {
        int r = m0 + warp_m * 32 + mi * 16 + (lane >> 2);
#pragma unroll
        for (int nj = 0; nj < 4; nj++) {
            int nc = nb + warp_n * 32 + nj * 8 + (lane & 3) * 2;
            if (r < M)
                *(float2*)&O[(size_t)r * 256 + nc] =
                    make_float2(acc[mi][nj][0], acc[mi][nj][1]);
            if (r + 8 < M)
                *(float2*)&O[(size_t)(r + 8) * 256 + nc] =
                    make_float2(acc[mi][nj][2], acc[mi][nj][3]);
        }
    }
}

// ---------------- layer-1 attention: warp/node, packed f32x2, lazy rescale ----------------
// leaky(v)*a = 0.6*v*a + 0.4*|v|*a  (exact for slope 0.2)
__global__ __launch_bounds__(256) void k_attn1(const float* __restrict__ att,
                                               const float* __restrict__ b1, int N)
{
    int gt = blockIdx.x * blockDim.x + threadIdx.x;
    int w = gt >> 5, lane = gt & 31;
    if (w >= N) return;
    int beg = g_offs[w], end = g_offs[w + 1];
    if (lane == 0) g_counts[w] = 0;      // reset for next replay

    const ulonglong2* pxr = (const ulonglong2*)(g_xr1 + (size_t)w * 256 + lane * 8);
    ulonglong2 xra = pxr[0], xrb = pxr[1];     // pairs (0,1)(2,3) | (4,5)(6,7)
    const ulonglong2* pat = (const ulonglong2*)(att + lane * 8);
    ulonglong2 ata = pat[0], atb = pat[1];

    float mx = -1e30f, dn = 0.f;
    U64 acc0 = 0, acc1 = 0, acc2 = 0, acc3 = 0;   // bit pattern 0 == (0.f,0.f)

    int p = beg;
    for (; p + 2 <= end; p += 2) {
        int s0i = g_src[p], s1i = g_src[p + 1];
        const ulonglong2* q0 = (const ulonglong2*)(g_xl1 + (size_t)s0i * 256 + lane * 8);
        const ulonglong2* q1 = (const ulonglong2*)(g_xl1 + (size_t)s1i * 256 + lane * 8);
        ulonglong2 xa = q0[0], xb = q0[1];
        ulonglong2 ya = q1[0], yb = q1[1];

        // edge 0 logit
        U64 v0 = add2(xa.x, xra.x), v1 = add2(xa.y, xra.y);
        U64 v2 = add2(xb.x, xrb.x), v3 = add2(xb.y, xrb.y);
        U64 sl0 = fma2(v0, ata.x, fma2(v1, ata.y, fma2(v2, atb.x, mul2(v3, atb.y))));
        U64 sa0 = fma2(abs2(v0), ata.x, fma2(abs2(v1), ata.y,
                  fma2(abs2(v2), atb.x, mul2(abs2(v3), atb.y))));
        // edge 1 logit
        U64 u0 = add2(ya.x, xra.x), u1 = add2(ya.y, xra.y);
        U64 u2 = add2(yb.x, xrb.x), u3 = add2(yb.y, xrb.y);
        U64 sl1 = fma2(u0, ata.x, fma2(u1, ata.y, fma2(u2, atb.x, mul2(u3, atb.y))));
        U64 sa1 = fma2(abs2(u0), ata.x, fma2(abs2(u1), ata.y,
                  fma2(abs2(u2), atb.x, mul2(abs2(u3), atb.y))));

        float2 l0 = unpack2(sl0), a0f = unpack2(sa0);
        float2 l1 = unpack2(sl1), a1f = unpack2(sa1);
        float s0 = 0.6f * (l0.x + l0.y) + 0.4f * (a0f.x + a0f.y);
        float s1 = 0.6f * (l1.x + l1.y) + 0.4f * (a1f.x + a1f.y);
        s0 += __shfl_xor_sync(0xffffffffu, s0, 4);
        s1 += __shfl_xor_sync(0xffffffffu, s1, 4);
        s0 += __shfl_xor_sync(0xffffffffu, s0, 2);
        s1 += __shfl_xor_sync(0xffffffffu, s1, 2);
        s0 += __shfl_xor_sync(0xffffffffu, s0, 1);
        s1 += __shfl_xor_sync(0xffffffffu, s1, 1);

        float mnew = fmaxf(s0, s1);
        if (mnew > mx) {                 // rare: rescale state
            float sc = __expf(mx - mnew);
            U64 sc2 = pack2(sc);
            dn *= sc;
            acc0 = mul2(acc0, sc2); acc1 = mul2(acc1, sc2);
            acc2 = mul2(acc2, sc2); acc3 = mul2(acc3, sc2);
            mx = mnew;
        }
        float e0 = __expf(s0 - mx), e1 = __expf(s1 - mx);
        dn += e0 + e1;
        U64 e02 = pack2(e0), e12 = pack2(e1);
        acc0 = fma2(xa.x, e02, fma2(ya.x, e12, acc0));
        acc1 = fma2(xa.y, e02, fma2(ya.y, e12, acc1));
        acc2 = fma2(xb.x, e02, fma2(yb.x, e12, acc2));
        acc3 = fma2(xb.y, e02, fma2(yb.y, e12, acc3));
    }
    if (p < end) {
        int src = g_src[p];
        const ulonglong2* q0 = (const ulonglong2*)(g_xl1 + (size_t)src * 256 + lane * 8);
        ulonglong2 xa = q0[0], xb = q0[1];
        U64 v0 = add2(xa.x, xra.x), v1 = add2(xa.y, xra.y);
        U64 v2 = add2(xb.x, xrb.x), v3 = add2(xb.y, xrb.y);
        U64 sl0 = fma2(v0, ata.x, fma2(v1, ata.y, fma2(v2, atb.x, mul2(v3, atb.y))));
        U64 sa0 = fma2(abs2(v0), ata.x, fma2(abs2(v1), ata.y,
                  fma2(abs2(v2), atb.x, mul2(abs2(v3), atb.y))));
        float2 l0 = unpack2(sl0), a0f = unpack2(sa0);
        float s0 = 0.6f * (l0.x + l0.y) + 0.4f * (a0f.x + a0f.y);
        s0 += __shfl_xor_sync(0xffffffffu, s0, 4);
        s0 += __shfl_xor_sync(0xffffffffu, s0, 2);
        s0 += __shfl_xor_sync(0xffffffffu, s0, 1);
        if (s0 > mx) {
            float sc = __expf(mx - s0);
            U64 sc2 = pack2(sc);
            dn *= sc;
            acc0 = mul2(acc0, sc2); acc1 = mul2(acc1, sc2);
            acc2 = mul2(acc2, sc2); acc3 = mul2(acc3, sc2);
            mx = s0;
        }
        float e0 = __expf(s0 - mx);
        dn += e0;
        U64 e02 = pack2(e0);
        acc0 = fma2(xa.x, e02, acc0);
        acc1 = fma2(xa.y, e02, acc1);
        acc2 = fma2(xb.x, e02, acc2);
        acc3 = fma2(xb.y, e02, acc3);
    }

    float inv = 1.f / (dn + 1e-16f);
    U64 inv2 = pack2(inv);
    const ulonglong2* pb = (const ulonglong2*)(b1 + lane * 8);
    ulonglong2 bb0 = pb[0], bb1 = pb[1];
    ulonglong2 o0, o1;
    o0.x = fma2(acc0, inv2, bb0.x);
    o0.y = fma2(acc1, inv2, bb0.y);
    o1.x = fma2(acc2, inv2, bb1.x);
    o1.y = fma2(acc3, inv2, bb1.y);
    ulonglong2* ph = (ulonglong2*)(g_h1 + (size_t)w * 256 + lane * 8);
    ph[0] = o0;
    ph[1] = o1;
}

// ---------------- batch-norm stats (float4, 64 quads x 4 row-groups) ----------------
__global__ __launch_bounds__(256) void k_bnstats(int N)
{
    __shared__ float sh_s[4 * 256];
    __shared__ float sh_q[4 * 256];
    int tid = threadIdx.x;
    int quad = tid & 63, rg = tid >> 6;
    int c4 = quad * 4;
    int rend = min(blockIdx.x * 128 + 128, N);
    float4 s = make_float4(0.f, 0.f, 0.f, 0.f);
    float4 q = make_float4(0.f, 0.f, 0.f, 0.f);
    for (int r = blockIdx.x * 128 + rg; r < rend; r += 4) {
        float4 v = *(const float4*)&g_h1[(size_t)r * 256 + c4];
        s.x += v.x; s.y += v.y; s.z += v.z; s.w += v.w;
        q.x += v.x * v.x; q.y += v.y * v.y; q.z += v.z * v.z; q.w += v.w * v.w;
    }
    *(float4*)&sh_s[rg * 256 + c4] = s;
    *(float4*)&sh_q[rg * 256 + c4] = q;
    __syncthreads();
    float ts = sh_s[tid] + sh_s[256 + tid] + sh_s[512 + tid] + sh_s[768 + tid];
    float tq = sh_q[tid] + sh_q[256 + tid] + sh_q[512 + tid] + sh_q[768 + tid];
    atomicAdd(&g_bn[tid], ts);
    atomicAdd(&g_bn[256 + tid], tq);
}

// ---------------- layer-2: BN-finalize prologue + BN+ELU + tf32 GEMM ----------------
#define SA2 36
#define SB2 88
__global__ __launch_bounds__(256) void k_gemm2_tc(
    const float* __restrict__ gamma, const float* __restrict__ beta,
    float* __restrict__ xl2, float* __restrict__ xr2, int M)
{
    __shared__ uint32_t As2[64 * SA2];
    __shared__ uint32_t Bs2[32 * SB2];
    __shared__ float sh_bns[256];
    __shared__ float sh_bnt[256];
    int tid = threadIdx.x;
    int lane = tid & 31, wid = tid >> 5;
    int warp_m = wid & 3, warp_n = wid >> 2;
    int m0 = blockIdx.x * 64;
    float acc[5][4] = {};

    {
        float invN = 1.f / (float)M;
        float mu = g_bn[tid] * invN;
        float var = g_bn[256 + tid] * invN - mu * mu;
        float rs = rsqrtf(var + 1e-5f);
        float s = gamma[tid] * rs;
        sh_bns[tid] = s;
        sh_bnt[tid] = beta[tid] - s * mu;
    }
    __syncthreads();

    for (int k0 = 0; k0 < 256; k0 += 32) {
#pragma unroll
        for (int i = 0; i < 2; i++) {
            int f = tid + i * 256;
            int r = f >> 3, c4 = (f & 7) * 4;
            int gr = m0 + r;
            float4 v = make_float4(0.f, 0.f, 0.f, 0.f);
            if (gr < M) v = *(const float4*)&g_h1[(size_t)gr * 256 + k0 + c4];
            float4 s4 = *(const float4*)&sh_bns[k0 + c4];
            float4 t4 = *(const float4*)&sh_bnt[k0 + c4];
            float e0 = s4.x * v.x + t4.x; e0 = e0 > 0.f ? e0 : (__expf(e0) - 1.f);
            float e1 = s4.y * v.y + t4.y; e1 = e1 > 0.f ? e1 : (__expf(e1) - 1.f);
            float e2 = s4.z * v.z + t4.z; e2 = e2 > 0.f ? e2 : (__expf(e2) - 1.f);
            float e3 = s4.w * v.w + t4.w; e3 = e3 > 0.f ? e3 : (__expf(e3) - 1.f);
            uint4 u = make_uint4(f2tf32(e0), f2tf32(e1), f2tf32(e2), f2tf32(e3));
            *(uint4*)&As2[r * SA2 + c4] = u;
        }
#pragma unroll
        for (int i = 0; i < 3; i++) {
            int f = tid + i * 256;
            if (f < 640) {
                int k = f / 20, n4 = (f % 20) * 4;
                *(uint4*)&Bs2[k * SB2 + n4] =
                    *(const uint4*)&g_W2t[(size_t)(k0 + k) * 80 + n4];
            }
        }
        __syncthreads();
#pragma unroll
        for (int ks = 0; ks < 4; ks++) {
            int kc = ks * 8 + (lane & 3);
            int r = warp_m * 16 + (lane >> 2);
            uint32_t a[4];
            a[0] = As2[r * SA2 + kc];
            a[1] = As2[(r + 8) * SA2 + kc];
            a[2] = As2[r * SA2 + kc + 4];
            a[3] = As2[(r + 8) * SA2 + kc + 4];
#pragma unroll
            for (int nj = 0; nj < 5; nj++) {
                int n = warp_n * 40 + nj * 8 + (lane >> 2);
                uint32_t b0 = Bs2[kc * SB2 + n];
                uint32_t b1 = Bs2[(kc + 4) * SB2 + n];
                mma_tf32(acc[nj], a, b0, b1);
            }
        }
        __syncthreads();
    }

    float* O = warp_n ? xr2 : xl2;
    int r = m0 + warp_m * 16 + (lane >> 2);
#pragma unroll
    for (int nj = 0; nj < 5; nj++) {
        int cc = nj * 8 + (lane & 3) * 2;
        if (r < M)
            *(float2*)&O[(size_t)r * 40 + cc] = make_float2(acc[nj][0], acc[nj][1]);
        if (r + 8 < M)
            *(float2*)&O[(size_t)(r + 8) * 40 + cc] = make_float2(acc[nj][2], acc[nj][3]);
    }
}

// ---------------- layer-2 fused single-pass online-softmax attention ----------------
__global__ __launch_bounds__(256) void k_attn2(const float* __restrict__ att2,
                                               const float* __restrict__ b2,
                                               float* __restrict__ out, int N)
{
    if (blockIdx.x == 0) {
        g_bn[threadIdx.x] = 0.f;
        g_bn[256 + threadIdx.x] = 0.f;
    }

    int gt = blockIdx.x * blockDim.x + threadIdx.x;
    int w = gt >> 5, lane = gt & 31;
    if (w >= N) return;
    int beg = g_offs[w], end = g_offs[w + 1];
    int sub = lane >> 3, l8 = lane & 7;

    float xr[5], at[5];
#pragma unroll
    for (int j = 0; j < 5; j++) {
        int c = l8 * 5 + j;
        xr[j] = g_xr2[(size_t)w * 40 + c];
        at[j] = att2[c];
    }

    float mx = -1e30f, dn = 0.f;
    float acc[5] = {};

    for (int p0 = beg; p0 < end; p0 += 4) {
        int p = p0 + sub;
        bool valid = (p < end);
        int src = g_src[valid ? p : beg];
        float xls[5];
        float s = 0.f;
#pragma unroll
        for (int j = 0; j < 5; j++) {
            xls[j] = g_xl2[(size_t)src * 40 + l8 * 5 + j];
            float v = xls[j] + xr[j];
            s += fmaxf(v, 0.2f * v) * at[j];
        }
        s += __shfl_xor_sync(0xffffffffu, s, 4);
        s += __shfl_xor_sync(0xffffffffu, s, 2);
        s += __shfl_xor_sync(0xffffffffu, s, 1);
        if (!valid) s = -1e30f;
        float mnew = fmaxf(mx, s);
        float sc = __expf(mx - mnew);
        float a  = valid ? __expf(s - mnew) : 0.f;
        dn = dn * sc + a;
#pragma unroll
        for (int j = 0; j < 5; j++) acc[j] = acc[j] * sc + a * xls[j];
        mx = mnew;
    }

#pragma unroll
    for (int off = 8; off <= 16; off <<= 1) {
        float mo  = __shfl_xor_sync(0xffffffffu, mx, off);
        float dno = __shfl_xor_sync(0xffffffffu, dn, off);
        float ao[5];
#pragma unroll
        for (int j = 0; j < 5; j++) ao[j] = __shfl_xor_sync(0xffffffffu, acc[j], off);
        float m = fmaxf(mx, mo);
        float f1 = __expf(mx - m), f2 = __expf(mo - m);
        dn = dn * f1 + dno * f2;
#pragma unroll
        for (int j = 0; j < 5; j++) acc[j] = acc[j] * f1 + ao[j] * f2;
        mx = m;
    }

    float inv = 1.f / (dn + 1e-16f);
    if (sub == 0) {
#pragma unroll
        for (int j = 0; j < 5; j++) {
            int c = l8 * 5 + j;
            out[(size_t)w * 40 + c] = acc[j] * inv + b2[c];
        }
    }
}

// ---------------- host launcher (single stream) ----------------
extern "C" void kernel_launch(void* const* d_in, const int* in_sizes, int n_in,
                              void* d_out, int out_size)
{
    const float* x      = (const float*)d_in[0];
    const int*   ei     = (const int*)  d_in[1];
    const float* Wl1    = (const float*)d_in[2];
    const float* Wr1    = (const float*)d_in[3];
    const float* att1   = (const float*)d_in[4];
    const float* b1     = (const float*)d_in[5];
    const float* gamma1 = (const float*)d_in[6];
    const float* beta1  = (const float*)d_in[7];
    const float* Wl2    = (const float*)d_in[8];
    const float* Wr2    = (const float*)d_in[9];
    const float* att2   = (const float*)d_in[10];
    const float* b2     = (const float*)d_in[11];
    float* out = (float*)d_out;

    int N = in_sizes[0] / 128;
    int E = in_sizes[1] / 2;
    int ET = E + N;
    int G = (ET + 3) / 4;

    void *pxl1, *pxr1, *pxl2, *pxr2;
    cudaGetSymbolAddress(&pxl1, g_xl1);
    cudaGetSymbolAddress(&pxr1, g_xr1);
    cudaGetSymbolAddress(&pxl2, g_xl2);
    cudaGetSymbolAddress(&pxr2, g_xr2);

    int CB  = (G + 255) / 256;
    int W1B = (128 * 512) / 256;
    int W2B = (256 * 80 + 255) / 256;
    int XB  = (N * 32 + 255) / 256;
    int PRE = CB + W1B + W2B + XB;

    k_pre<<<PRE, 256>>>(ei, E, N, G, CB, W1B, W2B, x, Wl1, Wr1, Wl2, Wr2);
    k_scan<<<1, 1024>>>(N);

    int FB = (G + 511) / 512;
    int GB = 4 * ((N + 127) / 128);
    k_fill_gemm1<<<FB + GB, 512>>>(ei, E, N, G, FB, (float*)pxl1, (float*)pxr1, N);

    k_attn1<<<(N + 7) / 8, 256>>>(att1, b1, N);

    k_bnstats<<<(N + 127) / 128, 256>>>(N);

    k_gemm2_tc<<<(N + 63) / 64, 256>>>(gamma1, beta1, (float*)pxl2, (float*)pxr2, N);

    k_attn2<<<(N + 7) / 8, 256>>>(att2, b2, out, N);
}